// round 1
// baseline (speedup 1.0000x reference)
#include <cuda_runtime.h>

#define NFEAT 64
#define KGRP  8
#define HK    64
#define KH    512   // KGRP*HK

// exp(z) staged once per launch into a device global (no allocs allowed).
__device__ float g_W[KH * NFEAT];

typedef unsigned long long ull;

__device__ __forceinline__ void ffma2(ull& acc, ull a, ull b) {
    asm("fma.rn.f32x2 %0, %1, %2, %0;" : "+l"(acc) : "l"(a), "l"(b));
}
__device__ __forceinline__ ull fadd2(ull a, ull b) {
    ull r; asm("add.rn.f32x2 %0, %1, %2;" : "=l"(r) : "l"(a), "l"(b)); return r;
}
__device__ __forceinline__ float2 unpack2(ull a) {
    float2 f; asm("mov.b64 {%0, %1}, %2;" : "=f"(f.x), "=f"(f.y) : "l"(a)); return f;
}
__device__ __forceinline__ ull pack2(float lo, float hi) {
    ull r; asm("mov.b64 %0, {%1, %2};" : "=l"(r) : "f"(lo), "f"(hi)); return r;
}

__global__ void expw_k(const float* __restrict__ z) {
    int i = blockIdx.x * blockDim.x + threadIdx.x;
    if (i < KH * NFEAT) g_W[i] = expf(z[i]);
}

__global__ void zeroA_k(float* __restrict__ A) {
    int i = threadIdx.x;
    if (i < KH) A[i] = 0.0f;
}

// 256 threads, 2 rows per thread, W + t + histogram in shared.
__global__ void __launch_bounds__(256, 1)
mnn_main(const float* __restrict__ x, const float* __restrict__ t,
         float* __restrict__ y, float* __restrict__ A, int n)
{
    extern __shared__ char smem_raw[];
    float* sW    = (float*)smem_raw;           // KH*NFEAT floats
    float* sT    = sW + KH * NFEAT;            // KH floats
    int*   sHist = (int*)(sT + KH);            // KH ints

    const int tid = threadIdx.x;

    // Stage W (exp(z)) into shared, coalesced 16B chunks.
    {
        const float4* gw4 = (const float4*)g_W;
        float4* sw4 = (float4*)sW;
        #pragma unroll 4
        for (int i = tid; i < KH * NFEAT / 4; i += 256) sw4[i] = gw4[i];
        for (int i = tid; i < KH; i += 256) { sT[i] = t[i]; sHist[i] = 0; }
    }
    __syncthreads();

    const int r0 = blockIdx.x * 512 + tid;
    const int r1 = r0 + 256;
    const bool v0 = r0 < n, v1 = r1 < n;

    // Load 2 x-rows into registers as f32x2 pairs (clamp OOB rows to row 0).
    ull xa[32], xb[32];
    {
        const float4* p0 = (const float4*)(x + (size_t)(v0 ? r0 : 0) * NFEAT);
        const float4* p1 = (const float4*)(x + (size_t)(v1 ? r1 : 0) * NFEAT);
        #pragma unroll
        for (int j = 0; j < 16; j++) {
            float4 a = p0[j];
            float4 b = p1[j];
            xa[2*j]   = pack2(a.x, a.y);
            xa[2*j+1] = pack2(a.z, a.w);
            xb[2*j]   = pack2(b.x, b.y);
            xb[2*j+1] = pack2(b.z, b.w);
        }
    }

    float minv0 =  3.4e38f, minv1 =  3.4e38f;
    int   mi0 = 0, mi1 = 0;                    // flattened k*HK+h at the min

    const longlong2* wbase = (const longlong2*)sW;

    for (int k = 0; k < KGRP; k++) {
        float gmax0 = -3.4e38f, gmax1 = -3.4e38f;
        int   hm0 = 0, hm1 = 0;
        const float* tk = sT + k * HK;

        for (int h = 0; h < HK; h++) {
            const longlong2* w = wbase + (k * HK + h) * (NFEAT / 4);
            ull a0 = 0, a1 = 0, a2 = 0, a3 = 0;
            ull b0 = 0, b1 = 0, b2 = 0, b3 = 0;
            #pragma unroll
            for (int j = 0; j < 16; j += 2) {
                longlong2 wa = w[j];
                longlong2 wb = w[j + 1];
                ffma2(a0, xa[2*j],     (ull)wa.x);
                ffma2(b0, xb[2*j],     (ull)wa.x);
                ffma2(a1, xa[2*j + 1], (ull)wa.y);
                ffma2(b1, xb[2*j + 1], (ull)wa.y);
                ffma2(a2, xa[2*j + 2], (ull)wb.x);
                ffma2(b2, xb[2*j + 2], (ull)wb.x);
                ffma2(a3, xa[2*j + 3], (ull)wb.y);
                ffma2(b3, xb[2*j + 3], (ull)wb.y);
            }
            float tv = tk[h];
            float2 s0 = unpack2(fadd2(fadd2(a0, a1), fadd2(a2, a3)));
            float2 s1 = unpack2(fadd2(fadd2(b0, b1), fadd2(b2, b3)));
            float g0 = (s0.x + s0.y) + tv;
            float g1 = (s1.x + s1.y) + tv;
            // strict > keeps FIRST max index (jnp.argmax semantics)
            if (g0 > gmax0) { gmax0 = g0; hm0 = h; }
            if (g1 > gmax1) { gmax1 = g1; hm1 = h; }
        }
        // strict < keeps FIRST min index (jnp.argmin semantics)
        if (gmax0 < minv0) { minv0 = gmax0; mi0 = k * HK + hm0; }
        if (gmax1 < minv1) { minv1 = gmax1; mi1 = k * HK + hm1; }
    }

    if (v0) { y[r0] = minv0; atomicAdd(&sHist[mi0], 1); }
    if (v1) { y[r1] = minv1; atomicAdd(&sHist[mi1], 1); }
    __syncthreads();

    for (int i = tid; i < KH; i += 256) {
        int c = sHist[i];
        if (c) atomicAdd(&A[i], (float)c);
    }
}

#define SMEM_BYTES ((KH * NFEAT + KH) * 4 + KH * 4)

extern "C" void kernel_launch(void* const* d_in, const int* in_sizes, int n_in,
                              void* d_out, int out_size)
{
    const float* x = (const float*)d_in[0];   // [N, 64]
    const float* z = (const float*)d_in[1];   // [8, 64, 64]
    const float* t = (const float*)d_in[2];   // [8, 64]
    const int n = in_sizes[0] / NFEAT;

    float* y = (float*)d_out;                 // [N]
    float* A = (float*)d_out + n;             // [8*64]

    cudaFuncSetAttribute(mnn_main, cudaFuncAttributeMaxDynamicSharedMemorySize,
                         SMEM_BYTES);

    expw_k<<<(KH * NFEAT + 255) / 256, 256>>>(z);
    zeroA_k<<<1, KH>>>(A);

    int blocks = (n + 511) / 512;
    mnn_main<<<blocks, 256, SMEM_BYTES>>>(x, t, y, A, n);
}

// round 3
// speedup vs baseline: 2.7220x; 2.7220x over previous
#include <cuda_runtime.h>
#include <cuda_bf16.h>
#include <cstdint>
#include <cfloat>

#define NFEAT 64
#define KH    512
#define TILE  256          // rows per CTA tile
#define WSTR  136          // padded row stride (bf16 elems) = 272B, conflict-free ldmatrix
#define GRID  152

// Prepped W image: 512 rows x [hi(64) | lo(64) | pad(8)] bf16
__device__ __align__(16) unsigned short g_Wimg[KH * WSTR];

// ── SMEM byte layout ──
#define SM_W 0
#define SM_X (KH * WSTR * 2)                 // 139264
#define SM_T (SM_X + TILE * WSTR * 2)        // 174080
#define SM_H (SM_T + KH * 4)                 // 176128
#define SM_TOTAL (SM_H + KH * 4)             // 178176

__device__ __forceinline__ uint32_t smem_u32(const void* p){
    uint32_t a; asm("{ .reg .u64 t; cvta.to.shared.u64 t, %1; cvt.u32.u64 %0, t; }" : "=r"(a) : "l"(p));
    return a;
}

#define LDM4(r, addr) asm volatile( \
    "ldmatrix.sync.aligned.m8n8.x4.shared.b16 {%0,%1,%2,%3}, [%4];" \
    : "=r"((r)[0]), "=r"((r)[1]), "=r"((r)[2]), "=r"((r)[3]) : "r"(addr))

#define LDM2(r, addr) asm volatile( \
    "ldmatrix.sync.aligned.m8n8.x2.shared.b16 {%0,%1}, [%2];" \
    : "=r"((r)[0]), "=r"((r)[1]) : "r"(addr))

#define MMA(c, a, b) asm volatile( \
    "mma.sync.aligned.m16n8k16.row.col.f32.bf16.bf16.f32 " \
    "{%0,%1,%2,%3}, {%4,%5,%6,%7}, {%8,%9}, {%0,%1,%2,%3};" \
    : "+f"((c)[0]), "+f"((c)[1]), "+f"((c)[2]), "+f"((c)[3]) \
    : "r"((a)[0]), "r"((a)[1]), "r"((a)[2]), "r"((a)[3]), "r"((b)[0]), "r"((b)[1]))

// ── prep: W = exp(z) split to bf16 hi/lo in padded layout ──
__global__ void prep_k(const float* __restrict__ z){
    int idx = blockIdx.x * blockDim.x + threadIdx.x;
    if (idx >= KH * NFEAT) return;
    int r = idx / NFEAT, c = idx % NFEAT;
    float w = expf(z[idx]);
    __nv_bfloat16 h = __float2bfloat16(w);
    __nv_bfloat16 l = __float2bfloat16(w - __bfloat162float(h));
    g_Wimg[r * WSTR + c]      = __bfloat16_as_ushort(h);
    g_Wimg[r * WSTR + 64 + c] = __bfloat16_as_ushort(l);
}

__global__ void zero_k(float* __restrict__ A){
    int i = threadIdx.x;
    if (i < KH) A[i] = 0.0f;
}

__device__ __forceinline__ void split_pack(float a, float b, uint32_t& hi, uint32_t& lo){
    __nv_bfloat16 ha = __float2bfloat16(a), hb = __float2bfloat16(b);
    __nv_bfloat16 la = __float2bfloat16(a - __bfloat162float(ha));
    __nv_bfloat16 lb = __float2bfloat16(b - __bfloat162float(hb));
    hi = (uint32_t)__bfloat16_as_ushort(ha) | ((uint32_t)__bfloat16_as_ushort(hb) << 16);
    lo = (uint32_t)__bfloat16_as_ushort(la) | ((uint32_t)__bfloat16_as_ushort(lb) << 16);
}

// ── main: persistent mma.sync GEMM + fused maxout/min/histogram ──
__global__ void __launch_bounds__(256, 1)
mnn_mma(const float* __restrict__ x, const float* __restrict__ t,
        float* __restrict__ y, float* __restrict__ A, int n, int ntiles)
{
    extern __shared__ char smem[];
    unsigned short* sX = (unsigned short*)(smem + SM_X);
    float*          sT = (float*)(smem + SM_T);
    int*            sH = (int*)(smem + SM_H);

    const int tid  = threadIdx.x;
    const int wid  = tid >> 5;
    const int lane = tid & 31;
    const int q    = lane & 3;

    // Stage W image (136 KB) + t + hist
    {
        const float4* src = (const float4*)g_Wimg;
        float4* dst = (float4*)(smem + SM_W);
        #pragma unroll 4
        for (int i = tid; i < KH * WSTR * 2 / 16; i += 256) dst[i] = src[i];
        for (int i = tid; i < KH; i += 256) { sT[i] = t[i]; sH[i] = 0; }
    }
    __syncthreads();

    const uint32_t sWa = smem_u32(smem + SM_W);
    const uint32_t sXa = smem_u32(sX);

    // Constant per-warp ldmatrix base addresses
    // A (x tile): 16x16 b16 tiles; lanes 0-15: rows, lanes 16-31: +16B col chunk
    const uint32_t abase0 = sXa + (uint32_t)(wid * 32 +      (lane & 15)) * (WSTR * 2) + ((lane >> 4) << 4);
    const uint32_t abase1 = sXa + (uint32_t)(wid * 32 + 16 + (lane & 15)) * (WSTR * 2) + ((lane >> 4) << 4);
    // B (W): 8x16 b16 tiles; lanes 0-7: neuron rows k0-7, lanes 8-15: k8-15
    const uint32_t brow = (uint32_t)(lane & 7) * (WSTR * 2) + (((lane >> 3) & 1) << 4);

    for (int tile = blockIdx.x; tile < ntiles; tile += gridDim.x) {
        const int rbase = tile * TILE;

        // ── stage x tile: 256 rows x 64 f32 → bf16 hi|lo in sX ──
        #pragma unroll 4
        for (int i = tid; i < TILE * 16; i += 256) {       // 16 float4 per row
            int row = i >> 4, c4 = i & 15;
            int gr = rbase + row; if (gr >= n) gr = n - 1;
            float4 v = ((const float4*)(x + (size_t)gr * NFEAT))[c4];
            uint32_t h01, l01, h23, l23;
            split_pack(v.x, v.y, h01, l01);
            split_pack(v.z, v.w, h23, l23);
            int b = row * WSTR + c4 * 4;
            *(uint32_t*)(sX + b)      = h01;
            *(uint32_t*)(sX + b + 2)  = h23;
            *(uint32_t*)(sX + b + 64) = l01;
            *(uint32_t*)(sX + b + 66) = l23;
        }
        __syncthreads();

        // ── load A fragments (constant across all 512 neurons) ──
        uint32_t ah[2][4][4], al[2][4][4];
        #pragma unroll
        for (int kc = 0; kc < 4; kc++) {
            LDM4(ah[0][kc], abase0 + kc * 32);
            LDM4(ah[1][kc], abase1 + kc * 32);
            LDM4(al[0][kc], abase0 + 128 + kc * 32);
            LDM4(al[1][kc], abase1 + 128 + kc * 32);
        }
        __syncthreads();   // A reads done; next tile's staging may proceed after compute

        float mn[4] = {FLT_MAX, FLT_MAX, FLT_MAX, FLT_MAX};
        int   mi[4] = {0, 0, 0, 0};

        #pragma unroll 1
        for (int g = 0; g < 8; g++) {
            float mx[4] = {-FLT_MAX, -FLT_MAX, -FLT_MAX, -FLT_MAX};
            int   ix[4] = {0, 0, 0, 0};

            #pragma unroll 1
            for (int s = 0; s < 8; s++) {
                const uint32_t bb = sWa + (uint32_t)(g * 64 + s * 8) * (WSTR * 2) + brow;
                uint32_t bh[4][2], bl[4][2];
                #pragma unroll
                for (int kc = 0; kc < 4; kc++) {
                    LDM2(bh[kc], bb + kc * 32);
                    LDM2(bl[kc], bb + 128 + kc * 32);
                }
                float acc[2][4] = {{0,0,0,0},{0,0,0,0}};
                #pragma unroll
                for (int kc = 0; kc < 4; kc++) { MMA(acc[0], ah[0][kc], bh[kc]); MMA(acc[1], ah[1][kc], bh[kc]); }
                #pragma unroll
                for (int kc = 0; kc < 4; kc++) { MMA(acc[0], al[0][kc], bh[kc]); MMA(acc[1], al[1][kc], bh[kc]); }
                #pragma unroll
                for (int kc = 0; kc < 4; kc++) { MMA(acc[0], ah[0][kc], bl[kc]); MMA(acc[1], ah[1][kc], bl[kc]); }

                // running argmax (ascending neuron idx, strict > keeps first)
                const int nb = g * 64 + s * 8 + q * 2;
                float2 tv = *(const float2*)(sT + nb);
                #pragma unroll
                for (int sl = 0; sl < 4; sl++) {
                    float v0 = acc[sl >> 1][(sl & 1) * 2]     + tv.x;
                    float v1 = acc[sl >> 1][(sl & 1) * 2 + 1] + tv.y;
                    if (v0 > mx[sl]) { mx[sl] = v0; ix[sl] = nb; }
                    if (v1 > mx[sl]) { mx[sl] = v1; ix[sl] = nb + 1; }
                }
            }
            // quad reduce (cols live on lane%4); tie → smaller idx
            #pragma unroll
            for (int sl = 0; sl < 4; sl++) {
                #pragma unroll
                for (int off = 1; off <= 2; off <<= 1) {
                    float ov = __shfl_xor_sync(0xFFFFFFFFu, mx[sl], off);
                    int   oi = __shfl_xor_sync(0xFFFFFFFFu, ix[sl], off);
                    if (ov > mx[sl] || (ov == mx[sl] && oi < ix[sl])) { mx[sl] = ov; ix[sl] = oi; }
                }
                if (mx[sl] < mn[sl]) { mn[sl] = mx[sl]; mi[sl] = ix[sl]; }
            }
        }

        // write y + histogram (one lane per quad; slots are row offsets 0,8,16,24)
        if (q == 0) {
            #pragma unroll
            for (int sl = 0; sl < 4; sl++) {
                int row = rbase + wid * 32 + (lane >> 2) + sl * 8;
                if (row < n) {
                    y[row] = mn[sl];
                    atomicAdd(&sH[mi[sl]], 1);
                }
            }
        }
        __syncthreads();   // sH updates + compute done before next tile restages sX
    }

    for (int i = tid; i < KH; i += 256) {
        int c = sH[i];
        if (c) atomicAdd(&A[i], (float)c);
    }
}

extern "C" void kernel_launch(void* const* d_in, const int* in_sizes, int n_in,
                              void* d_out, int out_size)
{
    const float* x = (const float*)d_in[0];   // [N, 64]
    const float* z = (const float*)d_in[1];   // [8, 64, 64]
    const float* t = (const float*)d_in[2];   // [8, 64]
    const int n = in_sizes[0] / NFEAT;
    const int ntiles = (n + TILE - 1) / TILE;

    float* y = (float*)d_out;
    float* A = (float*)d_out + n;

    cudaFuncSetAttribute(mnn_mma, cudaFuncAttributeMaxDynamicSharedMemorySize, SM_TOTAL);

    prep_k<<<(KH * NFEAT + 255) / 256, 256>>>(z);
    zero_k<<<1, KH>>>(A);

    int grid = ntiles < GRID ? ntiles : GRID;
    mnn_mma<<<grid, 256, SM_TOTAL>>>(x, t, y, A, n, ntiles);
}

// round 4
// speedup vs baseline: 2.8425x; 1.0443x over previous
#include <cuda_runtime.h>
#include <cuda_bf16.h>
#include <cstdint>
#include <cfloat>

#define NFEAT 64
#define KH    512
#define TILE  256          // rows per CTA tile
#define WSTR  136          // padded row stride (bf16 elems) = 272B, conflict-free ldmatrix
#define GRID  152

// Prepped W image: 512 rows x [hi(64) | lo(64) | pad(8)] bf16
__device__ __align__(16) unsigned short g_Wimg[KH * WSTR];

// ── SMEM byte layout ──
#define SM_W 0
#define SM_X (KH * WSTR * 2)
#define SM_T (SM_X + TILE * WSTR * 2)
#define SM_H (SM_T + KH * 4)
#define SM_TOTAL (SM_H + KH * 4)

__device__ __forceinline__ uint32_t smem_u32(const void* p){
    uint32_t a; asm("{ .reg .u64 t; cvta.to.shared.u64 t, %1; cvt.u32.u64 %0, t; }" : "=r"(a) : "l"(p));
    return a;
}

#define LDM4(r, addr) asm volatile( \
    "ldmatrix.sync.aligned.m8n8.x4.shared.b16 {%0,%1,%2,%3}, [%4];" \
    : "=r"((r)[0]), "=r"((r)[1]), "=r"((r)[2]), "=r"((r)[3]) : "r"(addr))

#define MMA(c, a, b0, b1) asm volatile( \
    "mma.sync.aligned.m16n8k16.row.col.f32.bf16.bf16.f32 " \
    "{%0,%1,%2,%3}, {%4,%5,%6,%7}, {%8,%9}, {%0,%1,%2,%3};" \
    : "+f"((c)[0]), "+f"((c)[1]), "+f"((c)[2]), "+f"((c)[3]) \
    : "r"((a)[0]), "r"((a)[1]), "r"((a)[2]), "r"((a)[3]), "r"(b0), "r"(b1))

// ── prep: W = exp(z) split to bf16 hi/lo in padded layout ──
__global__ void prep_k(const float* __restrict__ z){
    int idx = blockIdx.x * blockDim.x + threadIdx.x;
    if (idx >= KH * NFEAT) return;
    int r = idx / NFEAT, c = idx % NFEAT;
    float w = expf(z[idx]);
    __nv_bfloat16 h = __float2bfloat16(w);
    __nv_bfloat16 l = __float2bfloat16(w - __bfloat162float(h));
    g_Wimg[r * WSTR + c]      = __bfloat16_as_ushort(h);
    g_Wimg[r * WSTR + 64 + c] = __bfloat16_as_ushort(l);
}

__global__ void zero_k(float* __restrict__ A){
    int i = threadIdx.x;
    if (i < KH) A[i] = 0.0f;
}

__device__ __forceinline__ void split_pack(float a, float b, uint32_t& hi, uint32_t& lo){
    __nv_bfloat16 ha = __float2bfloat16(a), hb = __float2bfloat16(b);
    __nv_bfloat16 la = __float2bfloat16(a - __bfloat162float(ha));
    __nv_bfloat16 lb = __float2bfloat16(b - __bfloat162float(hb));
    hi = (uint32_t)__bfloat16_as_ushort(ha) | ((uint32_t)__bfloat16_as_ushort(hb) << 16);
    lo = (uint32_t)__bfloat16_as_ushort(la) | ((uint32_t)__bfloat16_as_ushort(lb) << 16);
}

// ── main: persistent mma.sync GEMM + fused maxout/min/histogram ──
__global__ void __launch_bounds__(256, 1)
mnn_mma(const float* __restrict__ x, const float* __restrict__ t,
        float* __restrict__ y, float* __restrict__ A, int n, int ntiles)
{
    extern __shared__ char smem[];
    unsigned short* sX = (unsigned short*)(smem + SM_X);
    float*          sT = (float*)(smem + SM_T);
    int*            sH = (int*)(smem + SM_H);

    const int tid  = threadIdx.x;
    const int wid  = tid >> 5;
    const int lane = tid & 31;
    const int q    = lane & 3;

    // Stage W image + t + hist
    {
        const float4* src = (const float4*)g_Wimg;
        float4* dst = (float4*)(smem + SM_W);
        #pragma unroll 4
        for (int i = tid; i < KH * WSTR * 2 / 16; i += 256) dst[i] = src[i];
        for (int i = tid; i < KH; i += 256) { sT[i] = t[i]; sH[i] = 0; }
    }
    __syncthreads();

    const uint32_t sWa = smem_u32(smem + SM_W);
    const uint32_t sXa = smem_u32(sX);

    // A (x) ldmatrix bases: 16x16 b16 tiles
    const uint32_t abase0 = sXa + (uint32_t)(wid * 32 +      (lane & 15)) * (WSTR * 2) + ((lane >> 4) << 4);
    const uint32_t abase1 = sXa + (uint32_t)(wid * 32 + 16 + (lane & 15)) * (WSTR * 2) + ((lane >> 4) << 4);
    // B (W) ldmatrix x4 lane offset: n16k16 = 4 8x8 tiles
    //  lanes 0-7:n0-7/k0, 8-15:n0-7/k8(+16B), 16-23:n8-15/k0, 24-31:n8-15/k8
    const uint32_t bpre = (uint32_t)((lane & 7) + ((lane >> 4) << 3)) * (WSTR * 2) + (((lane >> 3) & 1) << 4);

    for (int tile = blockIdx.x; tile < ntiles; tile += gridDim.x) {
        const int rbase = tile * TILE;

        // ── stage x tile: 256 rows x 64 f32 → bf16 hi|lo ──
        #pragma unroll 4
        for (int i = tid; i < TILE * 16; i += 256) {
            int row = i >> 4, c4 = i & 15;
            int gr = rbase + row; if (gr >= n) gr = n - 1;
            float4 v = ((const float4*)(x + (size_t)gr * NFEAT))[c4];
            uint32_t h01, l01, h23, l23;
            split_pack(v.x, v.y, h01, l01);
            split_pack(v.z, v.w, h23, l23);
            int b = row * WSTR + c4 * 4;
            *(uint32_t*)(sX + b)      = h01;
            *(uint32_t*)(sX + b + 2)  = h23;
            *(uint32_t*)(sX + b + 64) = l01;
            *(uint32_t*)(sX + b + 66) = l23;
        }
        __syncthreads();

        // A fragments (persist across all 512 neurons)
        uint32_t ah[2][4][4], al[2][4][4];
        #pragma unroll
        for (int kc = 0; kc < 4; kc++) {
            LDM4(ah[0][kc], abase0 + kc * 32);
            LDM4(ah[1][kc], abase1 + kc * 32);
            LDM4(al[0][kc], abase0 + 128 + kc * 32);
            LDM4(al[1][kc], abase1 + 128 + kc * 32);
        }
        __syncthreads();

        float mn[4] = {FLT_MAX, FLT_MAX, FLT_MAX, FLT_MAX};
        int   mi[4] = {0, 0, 0, 0};

        #pragma unroll 1
        for (int g = 0; g < 8; g++) {
            float mx[4] = {-FLT_MAX, -FLT_MAX, -FLT_MAX, -FLT_MAX};
            int   ix[4] = {0, 0, 0, 0};

            #pragma unroll 2
            for (int it = 0; it < 4; it++) {          // n16 sub-tiles
                const int nb = g * 64 + it * 16;
                const uint32_t bb = sWa + (uint32_t)nb * (WSTR * 2) + bpre;

                uint32_t bh[4][4], bl[4][4];
                #pragma unroll
                for (int kc = 0; kc < 4; kc++) {
                    LDM4(bh[kc], bb + kc * 32);
                    LDM4(bl[kc], bb + 128 + kc * 32);
                }

                // 8 independent chains of 6 MMAs: acc[mt][nh] split kc{0,1}/{2,3}
                float aA[2][2][4] = {{{0,0,0,0},{0,0,0,0}},{{0,0,0,0},{0,0,0,0}}};
                float aB[2][2][4] = {{{0,0,0,0},{0,0,0,0}},{{0,0,0,0},{0,0,0,0}}};
                #pragma unroll
                for (int kc = 0; kc < 2; kc++) {
                    #pragma unroll
                    for (int mt = 0; mt < 2; mt++) {
                        #pragma unroll
                        for (int nh = 0; nh < 2; nh++) {
                            MMA(aA[mt][nh], ah[mt][kc],   bh[kc][2*nh],   bh[kc][2*nh+1]);
                            MMA(aB[mt][nh], ah[mt][kc+2], bh[kc+2][2*nh], bh[kc+2][2*nh+1]);
                        }
                    }
                }
                #pragma unroll
                for (int kc = 0; kc < 2; kc++) {
                    #pragma unroll
                    for (int mt = 0; mt < 2; mt++) {
                        #pragma unroll
                        for (int nh = 0; nh < 2; nh++) {
                            MMA(aA[mt][nh], al[mt][kc],   bh[kc][2*nh],   bh[kc][2*nh+1]);
                            MMA(aB[mt][nh], al[mt][kc+2], bh[kc+2][2*nh], bh[kc+2][2*nh+1]);
                        }
                    }
                }
                #pragma unroll
                for (int kc = 0; kc < 2; kc++) {
                    #pragma unroll
                    for (int mt = 0; mt < 2; mt++) {
                        #pragma unroll
                        for (int nh = 0; nh < 2; nh++) {
                            MMA(aA[mt][nh], ah[mt][kc],   bl[kc][2*nh],   bl[kc][2*nh+1]);
                            MMA(aB[mt][nh], ah[mt][kc+2], bl[kc+2][2*nh], bl[kc+2][2*nh+1]);
                        }
                    }
                }

                // epilogue: 16 values, ascending neuron order per slot
                const int n0 = nb + 2 * q;
                float2 tv0 = *(const float2*)(sT + n0);
                float2 tv1 = *(const float2*)(sT + n0 + 8);
                #pragma unroll
                for (int mt = 0; mt < 2; mt++) {
                    #pragma unroll
                    for (int rh = 0; rh < 2; rh++) {
                        const int sl = mt * 2 + rh;
                        float v0 = (aA[mt][0][rh*2]   + tv0.x) + aB[mt][0][rh*2];
                        float v1 = (aA[mt][0][rh*2+1] + tv0.y) + aB[mt][0][rh*2+1];
                        float v2 = (aA[mt][1][rh*2]   + tv1.x) + aB[mt][1][rh*2];
                        float v3 = (aA[mt][1][rh*2+1] + tv1.y) + aB[mt][1][rh*2+1];
                        if (v0 > mx[sl]) { mx[sl] = v0; ix[sl] = n0; }
                        if (v1 > mx[sl]) { mx[sl] = v1; ix[sl] = n0 + 1; }
                        if (v2 > mx[sl]) { mx[sl] = v2; ix[sl] = n0 + 8; }
                        if (v3 > mx[sl]) { mx[sl] = v3; ix[sl] = n0 + 9; }
                    }
                }
            }

            // quad reduce (cols on lane%4); tie → smaller idx; then min over groups
            #pragma unroll
            for (int sl = 0; sl < 4; sl++) {
                #pragma unroll
                for (int off = 1; off <= 2; off <<= 1) {
                    float ov = __shfl_xor_sync(0xFFFFFFFFu, mx[sl], off);
                    int   oi = __shfl_xor_sync(0xFFFFFFFFu, ix[sl], off);
                    if (ov > mx[sl] || (ov == mx[sl] && oi < ix[sl])) { mx[sl] = ov; ix[sl] = oi; }
                }
                if (mx[sl] < mn[sl]) { mn[sl] = mx[sl]; mi[sl] = ix[sl]; }
            }
        }

        if (q == 0) {
            #pragma unroll
            for (int sl = 0; sl < 4; sl++) {
                int row = rbase + wid * 32 + (lane >> 2) + sl * 8;
                if (row < n) {
                    y[row] = mn[sl];
                    atomicAdd(&sH[mi[sl]], 1);
                }
            }
        }
        __syncthreads();
    }

    for (int i = tid; i < KH; i += 256) {
        int c = sH[i];
        if (c) atomicAdd(&A[i], (float)c);
    }
}

extern "C" void kernel_launch(void* const* d_in, const int* in_sizes, int n_in,
                              void* d_out, int out_size)
{
    const float* x = (const float*)d_in[0];   // [N, 64]
    const float* z = (const float*)d_in[1];   // [8, 64, 64]
    const float* t = (const float*)d_in[2];   // [8, 64]
    const int n = in_sizes[0] / NFEAT;
    const int ntiles = (n + TILE - 1) / TILE;

    float* y = (float*)d_out;
    float* A = (float*)d_out + n;

    cudaFuncSetAttribute(mnn_mma, cudaFuncAttributeMaxDynamicSharedMemorySize, SM_TOTAL);

    prep_k<<<(KH * NFEAT + 255) / 256, 256>>>(z);
    zero_k<<<1, KH>>>(A);

    int grid = ntiles < GRID ? ntiles : GRID;
    mnn_mma<<<grid, 256, SM_TOTAL>>>(x, t, y, A, n, ntiles);
}